// round 6
// baseline (speedup 1.0000x reference)
#include <cuda_runtime.h>

// GATv2 2-layer forward.
// x[2,1024,128], adj[2,1024,1024] i32, W1[64,128], a1[8], W2[8,64], a2[8]
// out[2,1024,8] f32
//
// Score identity: leaky(s) = 0.6*s + 0.4*|s|  =>
//   log2e*e(i,j,h) = C[i,h] + C[j,h] + sum_f (0.4*log2e*a_f)*|g_i,f + g_j,f|
// with C = 0.6*log2e*(a . g) precomputed per row/head.
// Max-free softmax (scores O(1); partials sum linearly).
// Adjacency packed to bitmask once (ballot).

#define LOG2E 1.4426950408889634f
typedef unsigned long long u64;

__device__ __forceinline__ float fexp2(float x) {
    float y;
    asm("ex2.approx.ftz.f32 %0, %1;" : "=f"(y) : "f"(x));
    return y;
}
__device__ __forceinline__ u64 add2(u64 a, u64 b) {
    u64 o; asm("add.rn.f32x2 %0,%1,%2;" : "=l"(o) : "l"(a), "l"(b)); return o;
}
__device__ __forceinline__ u64 mul2(u64 a, u64 b) {
    u64 o; asm("mul.rn.f32x2 %0,%1,%2;" : "=l"(o) : "l"(a), "l"(b)); return o;
}
__device__ __forceinline__ u64 fma2(u64 a, u64 b, u64 c) {
    u64 o; asm("fma.rn.f32x2 %0,%1,%2,%3;" : "=l"(o) : "l"(a), "l"(b), "l"(c)); return o;
}
__device__ __forceinline__ u64 pack2(float lo, float hi) {
    u64 o; asm("mov.b64 %0,{%1,%2};" : "=l"(o) : "f"(lo), "f"(hi)); return o;
}
__device__ __forceinline__ float2 unpack2(u64 a) {
    float2 r; asm("mov.b64 {%0,%1},%2;" : "=f"(r.x), "=f"(r.y) : "l"(a)); return r;
}

// scratch (allocation-free rule: __device__ globals)
__device__ float d_g1[2 * 1024 * 64];
__device__ float d_h1[2 * 1024 * 64];
__device__ float d_g2[2 * 1024 * 8];
__device__ float d_c1[2 * 1024 * 8];
__device__ float d_c2[2 * 1024];
__device__ unsigned d_bits[2 * 1024 * 32];

// ---------------------------------------------------------------------------
__global__ __launch_bounds__(256) void adj2bits(const int* __restrict__ adj,
                                                unsigned* __restrict__ bits) {
    int gw = (blockIdx.x * 256 + threadIdx.x) >> 5;
    int lane = threadIdx.x & 31;
    int v[8];
    size_t base = (size_t)gw * 8 * 32 + lane;
#pragma unroll
    for (int k = 0; k < 8; k++) v[k] = adj[base + k * 32];
#pragma unroll
    for (int k = 0; k < 8; k++) {
        unsigned m = __ballot_sync(0xffffffffu, v[k] != 0);
        if (lane == 0) bits[gw * 8 + k] = m;
    }
}

// C[t] = 0.6*log2e * dot(a, g[t*8 .. t*8+8))
__global__ __launch_bounds__(256) void ckern(const float* __restrict__ G,
                                             const float* __restrict__ A,
                                             float* __restrict__ C, int total) {
    int t = blockIdx.x * 256 + threadIdx.x;
    if (t >= total) return;
    const float4* g4 = (const float4*)(G + (size_t)t * 8);
    float4 v0 = g4[0], v1 = g4[1];
    float s = v0.x * __ldg(A + 0) + v0.y * __ldg(A + 1) + v0.z * __ldg(A + 2) +
              v0.w * __ldg(A + 3) + v1.x * __ldg(A + 4) + v1.y * __ldg(A + 5) +
              v1.z * __ldg(A + 6) + v1.w * __ldg(A + 7);
    C[t] = 0.6f * LOG2E * s;
}

// ---------------------------------------------------------------------------
template <int D, int K, int RPB>
__global__ __launch_bounds__(K* RPB) void gemm_nt(const float* __restrict__ X,
                                                  const float* __restrict__ W,
                                                  float* __restrict__ out, int M) {
    __shared__ float wsh[D * (K + 1)];
    for (int idx = threadIdx.x; idx < D * K; idx += blockDim.x) {
        int c = idx / D, d = idx % D;
        wsh[d * (K + 1) + c] = W[idx];
    }
    __syncthreads();
    int c = threadIdx.x % K;
    int r = blockIdx.x * RPB + threadIdx.x / K;
    if (r >= M) return;
    const float4* x4 = (const float4*)(X + (size_t)r * D);
    float acc = 0.f;
#pragma unroll
    for (int d4 = 0; d4 < D / 4; d4++) {
        float4 xv = __ldg(x4 + d4);
        acc = fmaf(xv.x, wsh[(d4 * 4 + 0) * (K + 1) + c], acc);
        acc = fmaf(xv.y, wsh[(d4 * 4 + 1) * (K + 1) + c], acc);
        acc = fmaf(xv.z, wsh[(d4 * 4 + 2) * (K + 1) + c], acc);
        acc = fmaf(xv.w, wsh[(d4 * 4 + 3) * (K + 1) + c], acc);
    }
    out[(size_t)r * K + c] = acc;
}

// ---------------------------------------------------------------------------
// attn layer 1: H=8, F=8. CTA = 256 thr = 8 warps = 2 row-PAIRS x 4 j-splits.
// Each warp processes TWO i-rows: one g_j/c_j smem read feeds two score+
// accumulate chains (halves crossbar traffic per pair; doubles ILP).
// lane = jg*8 + h. g tile stride 12/head (conflict-free LDS.128); C separate,
// stride 8 (conflict-free LDS.32). Staging q-permuted (conflict-free STS.128).
// ---------------------------------------------------------------------------
__global__ __launch_bounds__(256, 2) void attn1_kernel(
    const float* __restrict__ G, const unsigned* __restrict__ BITS,
    const float* __restrict__ C, const float* __restrict__ AW,
    float* __restrict__ OUT, int N) {
    constexpr int S = 96;   // 8 heads * 12-word stride
    constexpr int TJ = 128;

    extern __shared__ float smem[];
    float* gsh = smem;                 // TJ*S
    float* csh = smem + TJ * S;        // TJ*8
    float* psum = csh + TJ * 8;        // 8 warps * 2 rows * 8 h * 9

    int tid = threadIdx.x;
    int w = tid >> 5, lane = tid & 31;
    int p = w & 1, sp = w >> 1;        // pair, split
    int h = lane & 7, jg = lane >> 3;
    int base = sp * 4 + jg;            // [0,16)

    int iflat0 = blockIdx.x * 4 + 2 * p;   // rows 2p, 2p+1
    int iflat1 = iflat0 + 1;
    int b = iflat0 >> 10;

    const float* gpa = G + (size_t)iflat0 * 64 + h * 8;
    float4 x0 = *(const float4*)gpa;
    float4 x1 = *(const float4*)(gpa + 4);
    float4 y0 = *(const float4*)(gpa + 64);
    float4 y1 = *(const float4*)(gpa + 68);
    u64 gA01 = pack2(x0.x, x0.y), gA23 = pack2(x0.z, x0.w);
    u64 gA45 = pack2(x1.x, x1.y), gA67 = pack2(x1.z, x1.w);
    u64 gB01 = pack2(y0.x, y0.y), gB23 = pack2(y0.z, y0.w);
    u64 gB45 = pack2(y1.x, y1.y), gB67 = pack2(y1.z, y1.w);
    float ci0 = C[(size_t)iflat0 * 8 + h];
    float ci1 = C[(size_t)iflat1 * 8 + h];

    u64 aw[4];
#pragma unroll
    for (int k = 0; k < 4; k++)
        aw[k] = pack2(0.4f * LOG2E * __ldg(AW + 2 * k),
                      0.4f * LOG2E * __ldg(AW + 2 * k + 1));
    const u64 amask = 0x7fffffff7fffffffULL;

    float l0 = 0.f, l1 = 0.f;
    u64 aA01 = 0, aA23 = 0, aA45 = 0, aA67 = 0;
    u64 aB01 = 0, aB23 = 0, aB45 = 0, aB67 = 0;

    const float4* gbase = (const float4*)(G + (size_t)b * N * 64);
    const float* cbase = C + (size_t)b * N * 8;
    const unsigned* brow0 = BITS + (size_t)iflat0 * 32;
    const unsigned* brow1 = BITS + (size_t)iflat1 * 32;
    const float* gl = gsh + base * S + h * 12;
    const float* cl = csh + base * 8 + h;

    for (int jt = 0; jt < N; jt += TJ) {
        __syncthreads();
        const float4* src = gbase + (size_t)jt * 16;
        for (int idx = tid; idx < TJ * 16; idx += 256) {
            int j = idx >> 4, qidx = idx & 15;
            int q = ((qidx & 7) << 1) | (qidx >> 3);  // phase = even/odd q
            *(float4*)&gsh[j * S + (q >> 1) * 12 + (q & 1) * 4] = src[(j << 4) | q];
        }
        const float* csrc = cbase + (size_t)jt * 8;
        for (int idx = tid; idx < TJ * 8; idx += 256) csh[idx] = csrc[idx];
        __syncthreads();

        uint4 bw0 = *(const uint4*)(brow0 + (jt >> 5));
        uint4 bw1 = *(const uint4*)(brow1 + (jt >> 5));
#pragma unroll
        for (int k = 0; k < 8; k++) {
            const float* gr = gl + k * (16 * S);
            ulonglong2 v0 = *(const ulonglong2*)gr;
            ulonglong2 v1 = *(const ulonglong2*)(gr + 4);
            float cj = cl[k * 128];
            unsigned sh = base + ((k & 1) << 4);
            unsigned wv0 = (k < 2) ? bw0.x : (k < 4) ? bw0.y : (k < 6) ? bw0.z : bw0.w;
            unsigned wv1 = (k < 2) ? bw1.x : (k < 4) ? bw1.y : (k < 6) ? bw1.z : bw1.w;
            unsigned m0 = (wv0 >> sh) & 1u;
            unsigned m1 = (wv1 >> sh) & 1u;

            // row 0
            u64 sA = add2(gA01, v0.x);
            u64 dA = mul2(aw[0], sA & amask);
            sA = add2(gA23, v0.y); dA = fma2(aw[1], sA & amask, dA);
            sA = add2(gA45, v1.x); dA = fma2(aw[2], sA & amask, dA);
            sA = add2(gA67, v1.y); dA = fma2(aw[3], sA & amask, dA);
            // row 1
            u64 sB = add2(gB01, v0.x);
            u64 dB = mul2(aw[0], sB & amask);
            sB = add2(gB23, v0.y); dB = fma2(aw[1], sB & amask, dB);
            sB = add2(gB45, v1.x); dB = fma2(aw[2], sB & amask, dB);
            sB = add2(gB67, v1.y); dB = fma2(aw[3], sB & amask, dB);

            float2 eA = unpack2(dA), eB = unpack2(dB);
            float w0 = m0 ? fexp2((eA.x + eA.y) + (ci0 + cj)) : 0.f;
            float w1 = m1 ? fexp2((eB.x + eB.y) + (ci1 + cj)) : 0.f;
            l0 += w0; l1 += w1;
            u64 wp0 = pack2(w0, w0), wp1 = pack2(w1, w1);
            aA01 = fma2(wp0, v0.x, aA01); aA23 = fma2(wp0, v0.y, aA23);
            aA45 = fma2(wp0, v1.x, aA45); aA67 = fma2(wp0, v1.y, aA67);
            aB01 = fma2(wp1, v0.x, aB01); aB23 = fma2(wp1, v0.y, aB23);
            aB45 = fma2(wp1, v1.x, aB45); aB67 = fma2(wp1, v1.y, aB67);
        }
    }

    // intra-warp reduce across jg strips
    float2 fA01 = unpack2(aA01), fA23 = unpack2(aA23), fA45 = unpack2(aA45), fA67 = unpack2(aA67);
    float2 fB01 = unpack2(aB01), fB23 = unpack2(aB23), fB45 = unpack2(aB45), fB67 = unpack2(aB67);
    float A0[8] = {fA01.x, fA01.y, fA23.x, fA23.y, fA45.x, fA45.y, fA67.x, fA67.y};
    float A1[8] = {fB01.x, fB01.y, fB23.x, fB23.y, fB45.x, fB45.y, fB67.x, fB67.y};
#pragma unroll
    for (int off = 8; off < 32; off <<= 1) {
        l0 += __shfl_xor_sync(0xffffffffu, l0, off);
        l1 += __shfl_xor_sync(0xffffffffu, l1, off);
#pragma unroll
        for (int f = 0; f < 8; f++) {
            A0[f] += __shfl_xor_sync(0xffffffffu, A0[f], off);
            A1[f] += __shfl_xor_sync(0xffffffffu, A1[f], off);
        }
    }

    // cross-warp reduce across 4 split warps. psum idx: ((w*2+row)*8+h)*9
    if (jg == 0) {
        float* p0 = psum + ((w * 2 + 0) * 8 + h) * 9;
        p0[0] = l0;
#pragma unroll
        for (int f = 0; f < 8; f++) p0[1 + f] = A0[f];
        float* p1 = psum + ((w * 2 + 1) * 8 + h) * 9;
        p1[0] = l1;
#pragma unroll
        for (int f = 0; f < 8; f++) p1[1 + f] = A1[f];
    }
    __syncthreads();
    if (sp == 0 && jg == 0) {
#pragma unroll
        for (int rsel = 0; rsel < 2; rsel++) {
            float L = 0.f, A[8] = {0, 0, 0, 0, 0, 0, 0, 0};
#pragma unroll
            for (int ss = 0; ss < 4; ss++) {
                const float* pp = psum + (((ss * 2 + p) * 2 + rsel) * 8 + h) * 9;
                L += pp[0];
#pragma unroll
                for (int f = 0; f < 8; f++) A[f] += pp[1 + f];
            }
            float inv = 1.f / L;
            float o[8];
#pragma unroll
            for (int f = 0; f < 8; f++) {
                o[f] = A[f] * inv;
                o[f] = o[f] > 0.f ? o[f] : fexp2(o[f] * LOG2E) - 1.f;  // ELU
            }
            float* op = OUT + (size_t)(iflat0 + rsel) * 64 + h * 8;
            *(float4*)op = make_float4(o[0], o[1], o[2], o[3]);
            *(float4*)(op + 4) = make_float4(o[4], o[5], o[6], o[7]);
        }
    }
}

// ---------------------------------------------------------------------------
// attn layer 2: H=1, F=8. CTA = 256 thr = 8 warps = 8 rows. Whole g2 batch
// staged once; C separate stride-1. Lane L owns j = L + 32k; fully unrolled.
// ---------------------------------------------------------------------------
__global__ __launch_bounds__(256) void attn2_kernel(
    const float* __restrict__ G, const unsigned* __restrict__ BITS,
    const float* __restrict__ C, const float* __restrict__ AW,
    float* __restrict__ OUT, int N) {
    extern __shared__ float smem[];
    float* gsh = smem;            // N*12
    float* csh = smem + N * 12;   // N

    int tid = threadIdx.x;
    int w = tid >> 5, lane = tid & 31;
    int iflat = blockIdx.x * 8 + w;
    int b = iflat >> 10;

    const float4* gb = (const float4*)(G + (size_t)b * N * 8);
    const float* cb = C + (size_t)b * N;
    {
        int jb = tid & 127, q = tid >> 7;  // phase: same q, consecutive j
#pragma unroll
        for (int it = 0; it < 8; it++) {
            int j = jb + it * 128;
            *(float4*)&gsh[j * 12 + q * 4] = gb[j * 2 + q];
        }
    }
    for (int idx = tid; idx < N; idx += 256) csh[idx] = cb[idx];
    __syncthreads();

    const float* gp = G + (size_t)iflat * 8;
    float4 gi0 = *(const float4*)gp;
    float4 gi1 = *(const float4*)(gp + 4);
    u64 gp01 = pack2(gi0.x, gi0.y), gp23 = pack2(gi0.z, gi0.w);
    u64 gp45 = pack2(gi1.x, gi1.y), gp67 = pack2(gi1.z, gi1.w);
    float ci = C[iflat];

    u64 aw[4];
#pragma unroll
    for (int k = 0; k < 4; k++)
        aw[k] = pack2(0.4f * LOG2E * __ldg(AW + 2 * k),
                      0.4f * LOG2E * __ldg(AW + 2 * k + 1));
    const u64 amask = 0x7fffffff7fffffffULL;

    const uint4* b4 = (const uint4*)(BITS + (size_t)iflat * 32);
    const float* gl = gsh + lane * 12;
    const float* cl = csh + lane;

    float l = 0.f;
    u64 a01 = 0, a23 = 0, a45 = 0, a67 = 0;

#pragma unroll
    for (int kk = 0; kk < 8; kk++) {
        uint4 bw = b4[kk];
#pragma unroll
        for (int k2 = 0; k2 < 4; k2++) {
            const float* gr = gl + (kk * 4 + k2) * (32 * 12);
            ulonglong2 v0 = *(const ulonglong2*)gr;
            ulonglong2 v1 = *(const ulonglong2*)(gr + 4);
            float cj = cl[(kk * 4 + k2) * 32];
            unsigned wv = (k2 == 0) ? bw.x : (k2 == 1) ? bw.y : (k2 == 2) ? bw.z : bw.w;
            unsigned m = (wv >> lane) & 1u;

            u64 s01 = add2(gp01, v0.x), s23 = add2(gp23, v0.y);
            u64 s45 = add2(gp45, v1.x), s67 = add2(gp67, v1.y);
            u64 d = mul2(aw[0], s01 & amask);
            d = fma2(aw[1], s23 & amask, d);
            d = fma2(aw[2], s45 & amask, d);
            d = fma2(aw[3], s67 & amask, d);
            float2 ev = unpack2(d);
            float e = (ev.x + ev.y) + (ci + cj);
            float wgt = m ? fexp2(e) : 0.f;
            l += wgt;
            u64 wp = pack2(wgt, wgt);
            a01 = fma2(wp, v0.x, a01);
            a23 = fma2(wp, v0.y, a23);
            a45 = fma2(wp, v1.x, a45);
            a67 = fma2(wp, v1.y, a67);
        }
    }

    float2 f01 = unpack2(a01), f23 = unpack2(a23), f45 = unpack2(a45), f67 = unpack2(a67);
    float acc[8] = {f01.x, f01.y, f23.x, f23.y, f45.x, f45.y, f67.x, f67.y};
#pragma unroll
    for (int off = 1; off < 32; off <<= 1) {
        l += __shfl_xor_sync(0xffffffffu, l, off);
#pragma unroll
        for (int f = 0; f < 8; f++) acc[f] += __shfl_xor_sync(0xffffffffu, acc[f], off);
    }

    if (lane == 0) {
        float inv = 1.f / l;
        float* op = OUT + (size_t)iflat * 8;
        *(float4*)op = make_float4(acc[0] * inv, acc[1] * inv, acc[2] * inv, acc[3] * inv);
        *(float4*)(op + 4) = make_float4(acc[4] * inv, acc[5] * inv, acc[6] * inv, acc[7] * inv);
    }
}

// ---------------------------------------------------------------------------

extern "C" void kernel_launch(void* const* d_in, const int* in_sizes, int n_in,
                              void* d_out, int out_size) {
    const float* x = (const float*)d_in[0];
    const int* adj = (const int*)d_in[1];
    const float* W1 = (const float*)d_in[2];
    const float* a1 = (const float*)d_in[3];
    const float* W2 = (const float*)d_in[4];
    const float* a2 = (const float*)d_in[5];
    float* out = (float*)d_out;

    const int B = 2, N = 1024, M = B * N;

    float *g1, *h1, *g2, *c1, *c2;
    unsigned* bits;
    cudaGetSymbolAddress((void**)&g1, d_g1);
    cudaGetSymbolAddress((void**)&h1, d_h1);
    cudaGetSymbolAddress((void**)&g2, d_g2);
    cudaGetSymbolAddress((void**)&c1, d_c1);
    cudaGetSymbolAddress((void**)&c2, d_c2);
    cudaGetSymbolAddress((void**)&bits, d_bits);

    const int SMEM1 = (128 * 96 + 128 * 8 + 8 * 2 * 8 * 9) * 4;  // 57344
    const int SMEM2 = (N * 12 + N) * 4;                           // 53248
    cudaFuncSetAttribute((const void*)attn1_kernel,
                         cudaFuncAttributeMaxDynamicSharedMemorySize, SMEM1);
    cudaFuncSetAttribute((const void*)attn2_kernel,
                         cudaFuncAttributeMaxDynamicSharedMemorySize, SMEM2);

    adj2bits<<<1024, 256>>>(adj, bits);
    gemm_nt<128, 64, 4><<<M / 4, 256>>>(x, W1, g1, M);
    ckern<<<(M * 8) / 256, 256>>>(g1, a1, c1, M * 8);
    attn1_kernel<<<M / 4, 256, SMEM1>>>(g1, bits, c1, a1, h1, N);
    gemm_nt<64, 8, 32><<<M / 32, 256>>>(h1, W2, g2, M);
    ckern<<<M / 256, 256>>>(g2, a2, c2, M);
    attn2_kernel<<<M / 8, 256, SMEM2>>>(g2, bits, c2, a2, out, N);
}